// round 5
// baseline (speedup 1.0000x reference)
#include <cuda_runtime.h>
#include <math.h>

#define T_   1024
#define B_   8
#define E_   1024
#define H_   16
#define HD   64
#define NB   4
#define DIN  256
#define TOPK 16
#define ROWS (T_*B_)          // 8192
#define BE   (B_*E_)          // 8192
#define SCALING 0.125f        // 64^-0.5

// ---------- scratch (device globals; no runtime allocation) ----------
__device__ float g_q[ROWS * E_];
__device__ float g_k[ROWS * E_];
__device__ float g_v[ROWS * E_];
__device__ float g_ctx[ROWS * E_];

// ---------- packed f32x2 helpers (exact lane-wise IEEE rn) ----------
__device__ __forceinline__ void dup2(unsigned long long& d, float f) {
    asm("mov.b64 %0, {%1, %1};" : "=l"(d) : "r"(__float_as_uint(f)));
}
__device__ __forceinline__ void fma2(unsigned long long& d,
                                     unsigned long long a,
                                     unsigned long long b,
                                     unsigned long long c) {
    asm("fma.rn.f32x2 %0, %1, %2, %3;" : "=l"(d) : "l"(a), "l"(b), "l"(c));
}
__device__ __forceinline__ void unpack2(float& lo, float& hi, unsigned long long p) {
    unsigned l, h;
    asm("mov.b64 {%0, %1}, %2;" : "=r"(l), "=r"(h) : "l"(p));
    lo = __uint_as_float(l); hi = __uint_as_float(h);
}

// =====================================================================
// Block-diagonal group GEMM with FFMA2 (bitwise-identical to scalar:
// each (i,j) accumulator chain keeps identical order, rn per lane)
// =====================================================================
__global__ void __launch_bounds__(256) group_gemm(
    const float* __restrict__ X, const float* __restrict__ W,
    const float* __restrict__ bias, float* __restrict__ Y, float scale)
{
    const int nb = blockIdx.z;
    const int m0 = blockIdx.x * 128;
    const int n0 = blockIdx.y * 128;
    const float* Wn = W + nb * DIN * DIN;

    __shared__ __align__(16) float As[8][128];
    __shared__ __align__(16) float Bs[8][128];

    const int tid = threadIdx.x;
    const int ty = tid >> 4;
    const int tx = tid & 15;

    const int arow = tid >> 1;
    const int akc  = (tid & 1) * 4;
    const int bkr  = tid >> 5;
    const int bcol = (tid & 31) * 4;

    const float* Xb = X + (long)m0 * E_ + nb * DIN;

    unsigned long long accp[8][4];
#pragma unroll
    for (int i = 0; i < 8; i++)
#pragma unroll
        for (int j = 0; j < 4; j++) accp[i][j] = 0ull;

    for (int k0 = 0; k0 < DIN; k0 += 8) {
        float4 a4 = *(const float4*)(Xb + (long)arow * E_ + k0 + akc);
        float4 b4 = *(const float4*)(Wn + (k0 + bkr) * DIN + n0 + bcol);
        As[akc + 0][arow] = a4.x;
        As[akc + 1][arow] = a4.y;
        As[akc + 2][arow] = a4.z;
        As[akc + 3][arow] = a4.w;
        *(float4*)&Bs[bkr][bcol] = b4;
        __syncthreads();

#pragma unroll
        for (int kk = 0; kk < 8; kk++) {
            float af[8];
            *(float4*)(af)     = *(const float4*)&As[kk][ty * 8];
            *(float4*)(af + 4) = *(const float4*)&As[kk][ty * 8 + 4];
            ulonglong2 bp0 = *(const ulonglong2*)&Bs[kk][tx * 8];
            ulonglong2 bp1 = *(const ulonglong2*)&Bs[kk][tx * 8 + 4];
#pragma unroll
            for (int i = 0; i < 8; i++) {
                unsigned long long aa;
                dup2(aa, af[i]);
                fma2(accp[i][0], aa, bp0.x, accp[i][0]);
                fma2(accp[i][1], aa, bp0.y, accp[i][1]);
                fma2(accp[i][2], aa, bp1.x, accp[i][2]);
                fma2(accp[i][3], aa, bp1.y, accp[i][3]);
            }
        }
        __syncthreads();
    }

    float bj[8];
#pragma unroll
    for (int j = 0; j < 8; j++) bj[j] = bias[nb * DIN + n0 + tx * 8 + j];

#pragma unroll
    for (int i = 0; i < 8; i++) {
        float acc[8];
#pragma unroll
        for (int j = 0; j < 4; j++) unpack2(acc[2*j], acc[2*j+1], accp[i][j]);
        const long row = m0 + ty * 8 + i;
        float* yp = Y + row * E_ + nb * DIN + n0 + tx * 8;
        float4 o0, o1;
        o0.x = (acc[0] + bj[0]) * scale;
        o0.y = (acc[1] + bj[1]) * scale;
        o0.z = (acc[2] + bj[2]) * scale;
        o0.w = (acc[3] + bj[3]) * scale;
        o1.x = (acc[4] + bj[4]) * scale;
        o1.y = (acc[5] + bj[5]) * scale;
        o1.z = (acc[6] + bj[6]) * scale;
        o1.w = (acc[7] + bj[7]) * scale;
        *(float4*)yp       = o0;
        *(float4*)(yp + 4) = o1;
    }
}

// =====================================================================
// Fused attention. 1024 threads. K tile stored TRANSPOSED (kst[d][key])
// so adjacent keys pack into f32x2; 8 score warps (tile 8q x 128k) run
// FFMA2. Per-score accumulation order identical (d ascending, one fma
// per d) -> scores bitwise identical -> same top-k selection.
// =====================================================================
#define QT  32
#define KT  256
#define SP  1032   // padded score row stride (floats)
#define KSP 68     // padded q tile row stride
#define KTP 260    // transposed k tile row stride (keys + pad)
#define NTH 1024

// monotone map float->u32 (order preserving for finite floats)
__device__ __forceinline__ unsigned fmono(float f) {
    unsigned b = __float_as_uint(f);
    return (b & 0x80000000u) ? ~b : (b | 0x80000000u);
}
__device__ __forceinline__ float fdemono(unsigned m) {
    unsigned b = (m & 0x80000000u) ? (m & 0x7fffffffu) : ~m;
    return __uint_as_float(b);
}

__global__ void __launch_bounds__(NTH, 1) attn_kernel(
    const float* __restrict__ qg, const float* __restrict__ kg,
    const float* __restrict__ vg, float* __restrict__ ctxg)
{
    extern __shared__ float sm[];
    float* S    = sm;                      // QT*SP
    float* kst  = S + QT * SP;             // HD*KTP (transposed K tile)
    float* qs   = kst + HD * KTP;          // QT*KSP
    float* tpp  = qs + QT * KSP;           // 32*16 probs
    int*   tpi  = (int*)(tpp + QT * TOPK); // 32*16 indices

    const int tid = threadIdx.x;
    const int qt  = blockIdx.x;            // 0..31
    const int bh  = blockIdx.y;            // 0..127
    const int bb  = bh >> 4;
    const int hh  = bh & 15;
    const long base = (long)bb * E_ + hh * HD;

    const int lane = tid & 31;
    const int w    = tid >> 5;             // warp 0..31

    // ---- load q tile (32 x 64) once ----
    if (tid < QT * 16) {
        int r = tid >> 4, d4 = (tid & 15) * 4;
        float4 v4 = *(const float4*)(qg + (long)(qt * QT + r) * BE + base + d4);
        *(float4*)&qs[r * KSP + d4] = v4;
    }

    const int g = w >> 1;                  // q group (valid for w<8)
    const int s = w & 1;                   // k half
    const float* kbase = kst + s * 128 + 4 * lane;
    const float* qb    = qs + g * 8 * KSP;

    for (int kt = 0; kt < T_; kt += KT) {
        __syncthreads();
        // loader: warp covers 8 keys x 4 d-chunks (coalesced LDG,
        // 2-way-conflict transposed STS)
        for (int f = tid; f < KT * 16; f += NTH) {
            int kidx = f & 7;
            int d4x  = (f >> 3) & 15;
            int key  = (f >> 7) * 8 + kidx;
            float4 v4 = *(const float4*)(kg + (long)(kt + key) * BE + base + d4x * 4);
            kst[(d4x * 4 + 0) * KTP + key] = v4.x;
            kst[(d4x * 4 + 1) * KTP + key] = v4.y;
            kst[(d4x * 4 + 2) * KTP + key] = v4.z;
            kst[(d4x * 4 + 3) * KTP + key] = v4.w;
        }
        __syncthreads();

        if (w < 8) {
            unsigned long long acc[8][2];
#pragma unroll
            for (int i = 0; i < 8; i++) { acc[i][0] = 0ull; acc[i][1] = 0ull; }

#pragma unroll 4
            for (int d = 0; d < HD; d += 2) {
                ulonglong2 kp0 = *(const ulonglong2*)(kbase + (d + 0) * KTP);
                ulonglong2 kp1 = *(const ulonglong2*)(kbase + (d + 1) * KTP);
#pragma unroll
                for (int i = 0; i < 8; i++) {
                    float2 q2 = *(const float2*)(qb + i * KSP + d);
                    unsigned long long qq0, qq1;
                    dup2(qq0, q2.x);
                    dup2(qq1, q2.y);
                    fma2(acc[i][0], qq0, kp0.x, acc[i][0]);
                    fma2(acc[i][1], qq0, kp0.y, acc[i][1]);
                    fma2(acc[i][0], qq1, kp1.x, acc[i][0]);
                    fma2(acc[i][1], qq1, kp1.y, acc[i][1]);
                }
            }

#pragma unroll
            for (int i = 0; i < 8; i++) {
                float* Sp = &S[(g * 8 + i) * SP + kt + s * 128 + 4 * lane];
                *(unsigned long long*)(Sp)     = acc[i][0];
                *(unsigned long long*)(Sp + 2) = acc[i][1];
            }
        }
    }
    __syncthreads();

    // ---- per-row top-16 + softmax: warp w owns row w (unchanged R4) ----
    {
        float* Sr = S + w * SP;

        float v0 = -INFINITY, v1 = -INFINITY, v2 = -INFINITY, v3 = -INFINITY;
        int   p0 = 0, p1 = 0, p2 = 0, p3 = 0;
#pragma unroll 8
        for (int t = 0; t < 32; t++) {
            float nv = Sr[lane + 32 * t]; int np = lane + 32 * t;
            if (nv > v3) {
                if (nv > v1) {
                    if (nv > v0) { v3=v2;p3=p2; v2=v1;p2=p1; v1=v0;p1=p0; v0=nv;p0=np; }
                    else         { v3=v2;p3=p2; v2=v1;p2=p1; v1=nv;p1=np; }
                } else {
                    if (nv > v2) { v3=v2;p3=p2; v2=nv;p2=np; }
                    else         { v3=nv;p3=np; }
                }
            }
        }
        int cnt = 4;

        unsigned kb = fmono(v0);
        unsigned mk = __reduce_max_sync(0xffffffffu, kb);
        unsigned cp = (kb == mk) ? (unsigned)p0 : 0xffffffffu;
        unsigned bp = __reduce_min_sync(0xffffffffu, cp);
        const float m = fdemono(mk);

        float s0 = 0.f, s1 = 0.f, s2 = 0.f, s3 = 0.f;
#pragma unroll
        for (int t = 0; t < 32; t += 4) {
            s0 += __expf(Sr[lane + 32 * (t + 0)] - m);
            s1 += __expf(Sr[lane + 32 * (t + 1)] - m);
            s2 += __expf(Sr[lane + 32 * (t + 2)] - m);
            s3 += __expf(Sr[lane + 32 * (t + 3)] - m);
        }
        float sum = (s0 + s1) + (s2 + s3);
#pragma unroll
        for (int o = 16; o; o >>= 1) sum += __shfl_xor_sync(~0u, sum, o);
        const float inv = 1.0f / sum;

        if (lane == 0) { tpi[w * TOPK] = (int)bp; tpp[w * TOPK] = inv; }
        if ((bp & 31) == lane) {
            Sr[bp] = -INFINITY;
            v0=v1;p0=p1; v1=v2;p1=p2; v2=v3;p2=p3; v3=-INFINITY;
            if (--cnt == 0) {
                v0=v1=v2=v3=-INFINITY; p0=p1=p2=p3=0;
                for (int t = 0; t < 32; t++) {
                    float nv = Sr[lane + 32 * t]; int np = lane + 32 * t;
                    if (nv > v3) {
                        if (nv > v1) {
                            if (nv > v0) { v3=v2;p3=p2; v2=v1;p2=p1; v1=v0;p1=p0; v0=nv;p0=np; }
                            else         { v3=v2;p3=p2; v2=v1;p2=p1; v1=nv;p1=np; }
                        } else {
                            if (nv > v2) { v3=v2;p3=p2; v2=nv;p2=np; }
                            else         { v3=nv;p3=np; }
                        }
                    }
                }
                cnt = 4;
            }
        }

        for (int it = 1; it < TOPK; it++) {
            kb = fmono(v0);
            mk = __reduce_max_sync(0xffffffffu, kb);
            cp = (kb == mk) ? (unsigned)p0 : 0xffffffffu;
            bp = __reduce_min_sync(0xffffffffu, cp);
            if (lane == 0) {
                tpi[w * TOPK + it] = (int)bp;
                tpp[w * TOPK + it] = __expf(fdemono(mk) - m) * inv;
            }
            if ((bp & 31) == lane) {
                Sr[bp] = -INFINITY;
                v0=v1;p0=p1; v1=v2;p1=p2; v2=v3;p2=p3; v3=-INFINITY;
                if (--cnt == 0) {
                    v0=v1=v2=v3=-INFINITY; p0=p1=p2=p3=0;
                    for (int t = 0; t < 32; t++) {
                        float nv = Sr[lane + 32 * t]; int np = lane + 32 * t;
                        if (nv > v3) {
                            if (nv > v1) {
                                if (nv > v0) { v3=v2;p3=p2; v2=v1;p2=p1; v1=v0;p1=p0; v0=nv;p0=np; }
                                else         { v3=v2;p3=p2; v2=v1;p2=p1; v1=nv;p1=np; }
                            } else {
                                if (nv > v2) { v3=v2;p3=p2; v2=nv;p2=np; }
                                else         { v3=nv;p3=np; }
                            }
                        }
                    }
                    cnt = 4;
                }
            }
        }
    }
    __syncthreads();

    // ---- sparse ctx: 16-key gather per query row ----
    const int cr = w;
    const int d0 = lane * 2;
    float c0 = 0.f, c1 = 0.f;
#pragma unroll
    for (int i = 0; i < TOPK; i++) {
        const int   idx = tpi[cr * TOPK + i];
        const float p   = tpp[cr * TOPK + i];
        float2 a = *(const float2*)(vg + (long)idx * BE + base + d0);
        c0 = fmaf(p, a.x, c0); c1 = fmaf(p, a.y, c1);
    }
    *(float2*)(ctxg + (long)(qt * QT + cr) * BE + base + d0) = make_float2(c0, c1);
}

// =====================================================================
// launch
// =====================================================================
static const size_t ATTN_SMEM =
    (size_t)(QT * SP + HD * KTP + QT * KSP + QT * TOPK + QT * TOPK) * 4;

extern "C" void kernel_launch(void* const* d_in, const int* in_sizes, int n_in,
                              void* d_out, int out_size)
{
    const float* query  = (const float*)d_in[0];
    const float* key_in = (const float*)d_in[1];
    const float* value  = (const float*)d_in[2];
    const float* Wq = (const float*)d_in[3];
    const float* bq = (const float*)d_in[4];
    const float* Wk = (const float*)d_in[5];
    const float* bk = (const float*)d_in[6];
    const float* Wv = (const float*)d_in[7];
    const float* bv = (const float*)d_in[8];
    const float* Wo = (const float*)d_in[9];
    const float* bo = (const float*)d_in[10];
    float* out = (float*)d_out;

    float *pq, *pk, *pv, *pctx;
    cudaGetSymbolAddress((void**)&pq,   g_q);
    cudaGetSymbolAddress((void**)&pk,   g_k);
    cudaGetSymbolAddress((void**)&pv,   g_v);
    cudaGetSymbolAddress((void**)&pctx, g_ctx);

    cudaFuncSetAttribute(attn_kernel,
                         cudaFuncAttributeMaxDynamicSharedMemorySize,
                         (int)ATTN_SMEM);

    dim3 gg(ROWS / 128, DIN / 128, NB);
    group_gemm<<<gg, 256>>>(query,  Wq, bq, pq, SCALING);
    group_gemm<<<gg, 256>>>(key_in, Wk, bk, pk, 1.0f);
    group_gemm<<<gg, 256>>>(value,  Wv, bv, pv, 1.0f);

    dim3 ag(T_ / QT, B_ * H_);
    attn_kernel<<<ag, NTH, ATTN_SMEM>>>(pq, pk, pv, pctx);

    group_gemm<<<gg, 256>>>(pctx, Wo, bo, out, 1.0f);
}

// round 6
// speedup vs baseline: 1.0788x; 1.0788x over previous
#include <cuda_runtime.h>
#include <math.h>

#define T_   1024
#define B_   8
#define E_   1024
#define H_   16
#define HD   64
#define NB   4
#define DIN  256
#define TOPK 16
#define ROWS (T_*B_)          // 8192
#define BE   (B_*E_)          // 8192
#define SCALING 0.125f        // 64^-0.5

// ---------- scratch (device globals; no runtime allocation) ----------
__device__ float g_q[ROWS * E_];
__device__ float g_k[ROWS * E_];
__device__ float g_v[ROWS * E_];
__device__ float g_ctx[ROWS * E_];

// ---------- packed f32x2 helpers (exact lane-wise IEEE rn) ----------
__device__ __forceinline__ void dup2(unsigned long long& d, float f) {
    asm("mov.b64 %0, {%1, %1};" : "=l"(d) : "r"(__float_as_uint(f)));
}
__device__ __forceinline__ void fma2(unsigned long long& d,
                                     unsigned long long a,
                                     unsigned long long b,
                                     unsigned long long c) {
    asm("fma.rn.f32x2 %0, %1, %2, %3;" : "=l"(d) : "l"(a), "l"(b), "l"(c));
}
__device__ __forceinline__ void unpack2(float& lo, float& hi, unsigned long long p) {
    unsigned l, h;
    asm("mov.b64 {%0, %1}, %2;" : "=r"(l), "=r"(h) : "l"(p));
    lo = __uint_as_float(l); hi = __uint_as_float(h);
}

// =====================================================================
// Block-diagonal group GEMM with FFMA2 (bitwise-identical to scalar)
// =====================================================================
__global__ void __launch_bounds__(256) group_gemm(
    const float* __restrict__ X, const float* __restrict__ W,
    const float* __restrict__ bias, float* __restrict__ Y, float scale)
{
    const int nb = blockIdx.z;
    const int m0 = blockIdx.x * 128;
    const int n0 = blockIdx.y * 128;
    const float* Wn = W + nb * DIN * DIN;

    __shared__ __align__(16) float As[8][128];
    __shared__ __align__(16) float Bs[8][128];

    const int tid = threadIdx.x;
    const int ty = tid >> 4;
    const int tx = tid & 15;

    const int arow = tid >> 1;
    const int akc  = (tid & 1) * 4;
    const int bkr  = tid >> 5;
    const int bcol = (tid & 31) * 4;

    const float* Xb = X + (long)m0 * E_ + nb * DIN;

    unsigned long long accp[8][4];
#pragma unroll
    for (int i = 0; i < 8; i++)
#pragma unroll
        for (int j = 0; j < 4; j++) accp[i][j] = 0ull;

    for (int k0 = 0; k0 < DIN; k0 += 8) {
        float4 a4 = *(const float4*)(Xb + (long)arow * E_ + k0 + akc);
        float4 b4 = *(const float4*)(Wn + (k0 + bkr) * DIN + n0 + bcol);
        As[akc + 0][arow] = a4.x;
        As[akc + 1][arow] = a4.y;
        As[akc + 2][arow] = a4.z;
        As[akc + 3][arow] = a4.w;
        *(float4*)&Bs[bkr][bcol] = b4;
        __syncthreads();

#pragma unroll
        for (int kk = 0; kk < 8; kk++) {
            float af[8];
            *(float4*)(af)     = *(const float4*)&As[kk][ty * 8];
            *(float4*)(af + 4) = *(const float4*)&As[kk][ty * 8 + 4];
            ulonglong2 bp0 = *(const ulonglong2*)&Bs[kk][tx * 8];
            ulonglong2 bp1 = *(const ulonglong2*)&Bs[kk][tx * 8 + 4];
#pragma unroll
            for (int i = 0; i < 8; i++) {
                unsigned long long aa;
                dup2(aa, af[i]);
                fma2(accp[i][0], aa, bp0.x, accp[i][0]);
                fma2(accp[i][1], aa, bp0.y, accp[i][1]);
                fma2(accp[i][2], aa, bp1.x, accp[i][2]);
                fma2(accp[i][3], aa, bp1.y, accp[i][3]);
            }
        }
        __syncthreads();
    }

    float bj[8];
#pragma unroll
    for (int j = 0; j < 8; j++) bj[j] = bias[nb * DIN + n0 + tx * 8 + j];

#pragma unroll
    for (int i = 0; i < 8; i++) {
        float acc[8];
#pragma unroll
        for (int j = 0; j < 4; j++) unpack2(acc[2*j], acc[2*j+1], accp[i][j]);
        const long row = m0 + ty * 8 + i;
        float* yp = Y + row * E_ + nb * DIN + n0 + tx * 8;
        float4 o0, o1;
        o0.x = (acc[0] + bj[0]) * scale;
        o0.y = (acc[1] + bj[1]) * scale;
        o0.z = (acc[2] + bj[2]) * scale;
        o0.w = (acc[3] + bj[3]) * scale;
        o1.x = (acc[4] + bj[4]) * scale;
        o1.y = (acc[5] + bj[5]) * scale;
        o1.z = (acc[6] + bj[6]) * scale;
        o1.w = (acc[7] + bj[7]) * scale;
        *(float4*)yp       = o0;
        *(float4*)(yp + 4) = o1;
    }
}

// =====================================================================
// Fused attention (R4 structure). K tile key-major, 64 floats/key,
// 16B chunks XOR-swizzled (chunk' = d4 ^ (key&7)) -> conflict-free
// score-phase LDS.128. Accumulation order identical to R4 -> bitwise
// same scores -> same top-k selection.
// =====================================================================
#define QT  32
#define KT  256
#define SP  1032   // padded score row stride (floats)
#define KSP 68     // padded q tile row stride
#define NTH 1024

// monotone map float->u32 (order preserving for finite floats)
__device__ __forceinline__ unsigned fmono(float f) {
    unsigned b = __float_as_uint(f);
    return (b & 0x80000000u) ? ~b : (b | 0x80000000u);
}
__device__ __forceinline__ float fdemono(unsigned m) {
    unsigned b = (m & 0x80000000u) ? (m & 0x7fffffffu) : ~m;
    return __uint_as_float(b);
}

__global__ void __launch_bounds__(NTH, 1) attn_kernel(
    const float* __restrict__ qg, const float* __restrict__ kg,
    const float* __restrict__ vg, float* __restrict__ ctxg)
{
    extern __shared__ float sm[];
    float* S    = sm;                      // QT*SP
    float* ks   = S + QT * SP;             // KT*64 (swizzled key-major)
    float* qs   = ks + KT * 64;            // QT*KSP
    float* tpp  = qs + QT * KSP;           // 32*16 probs
    int*   tpi  = (int*)(tpp + QT * TOPK); // 32*16 indices

    const int tid = threadIdx.x;
    const int qt  = blockIdx.x;            // 0..31
    const int bh  = blockIdx.y;            // 0..127
    const int bb  = bh >> 4;
    const int hh  = bh & 15;
    const long base = (long)bb * E_ + hh * HD;

    const int lane = tid & 31;
    const int w    = tid >> 5;             // warp 0..31

    // ---- load q tile (32 x 64) once ----
    if (tid < QT * 16) {
        int r = tid >> 4, d4 = (tid & 15) * 4;
        float4 v4 = *(const float4*)(qg + (long)(qt * QT + r) * BE + base + d4);
        *(float4*)&qs[r * KSP + d4] = v4;
    }

    // ---- scores: 32 x 1024; warps 0-15 compute (4q x 128k each) ----
    const int g = w >> 1;                  // q group (valid for w<16)
    const int s = w & 1;                   // k half
    const int lane7 = lane & 7;
    const int key0 = s * 128 + lane;       // + 32*j
    const float* qb = qs + (g & 7) * 4 * KSP;

    for (int kt = 0; kt < T_; kt += KT) {
        __syncthreads();
        // loader: key-major, XOR-swizzled chunk placement
        for (int f = tid; f < KT * 16; f += NTH) {
            int key = f >> 4, d4x = f & 15;
            float4 v4 = *(const float4*)(kg + (long)(kt + key) * BE + base + d4x * 4);
            *(float4*)&ks[key * 64 + ((d4x ^ (key & 7)) << 2)] = v4;
        }
        __syncthreads();

        if (w < 16) {
            float acc[4][4];
#pragma unroll
            for (int i = 0; i < 4; i++)
#pragma unroll
                for (int j = 0; j < 4; j++) acc[i][j] = 0.0f;

#pragma unroll 4
            for (int d4 = 0; d4 < 16; d4++) {
                const int c = ((d4 ^ lane7) << 2);
                float4 k4[4];
#pragma unroll
                for (int j = 0; j < 4; j++)
                    k4[j] = *(const float4*)&ks[(key0 + 32 * j) * 64 + c];
#pragma unroll
                for (int i = 0; i < 4; i++) {
                    float4 q4 = *(const float4*)(qb + i * KSP + d4 * 4);
#pragma unroll
                    for (int j = 0; j < 4; j++) {
                        acc[i][j] = fmaf(q4.x, k4[j].x, acc[i][j]);
                        acc[i][j] = fmaf(q4.y, k4[j].y, acc[i][j]);
                        acc[i][j] = fmaf(q4.z, k4[j].z, acc[i][j]);
                        acc[i][j] = fmaf(q4.w, k4[j].w, acc[i][j]);
                    }
                }
            }

#pragma unroll
            for (int i = 0; i < 4; i++)
#pragma unroll
                for (int j = 0; j < 4; j++)
                    S[(g * 4 + i) * SP + kt + s * 128 + lane + 32 * j] = acc[i][j];
        }
    }
    __syncthreads();

    // ---- per-row top-16 + softmax: warp w owns row w (unchanged R4) ----
    {
        float* Sr = S + w * SP;

        float v0 = -INFINITY, v1 = -INFINITY, v2 = -INFINITY, v3 = -INFINITY;
        int   p0 = 0, p1 = 0, p2 = 0, p3 = 0;
#pragma unroll 8
        for (int t = 0; t < 32; t++) {
            float nv = Sr[lane + 32 * t]; int np = lane + 32 * t;
            if (nv > v3) {
                if (nv > v1) {
                    if (nv > v0) { v3=v2;p3=p2; v2=v1;p2=p1; v1=v0;p1=p0; v0=nv;p0=np; }
                    else         { v3=v2;p3=p2; v2=v1;p2=p1; v1=nv;p1=np; }
                } else {
                    if (nv > v2) { v3=v2;p3=p2; v2=nv;p2=np; }
                    else         { v3=nv;p3=np; }
                }
            }
        }
        int cnt = 4;

        unsigned kb = fmono(v0);
        unsigned mk = __reduce_max_sync(0xffffffffu, kb);
        unsigned cp = (kb == mk) ? (unsigned)p0 : 0xffffffffu;
        unsigned bp = __reduce_min_sync(0xffffffffu, cp);
        const float m = fdemono(mk);

        float s0 = 0.f, s1 = 0.f, s2 = 0.f, s3 = 0.f;
#pragma unroll
        for (int t = 0; t < 32; t += 4) {
            s0 += __expf(Sr[lane + 32 * (t + 0)] - m);
            s1 += __expf(Sr[lane + 32 * (t + 1)] - m);
            s2 += __expf(Sr[lane + 32 * (t + 2)] - m);
            s3 += __expf(Sr[lane + 32 * (t + 3)] - m);
        }
        float sum = (s0 + s1) + (s2 + s3);
#pragma unroll
        for (int o = 16; o; o >>= 1) sum += __shfl_xor_sync(~0u, sum, o);
        const float inv = 1.0f / sum;

        if (lane == 0) { tpi[w * TOPK] = (int)bp; tpp[w * TOPK] = inv; }
        if ((bp & 31) == lane) {
            Sr[bp] = -INFINITY;
            v0=v1;p0=p1; v1=v2;p1=p2; v2=v3;p2=p3; v3=-INFINITY;
            if (--cnt == 0) {
                v0=v1=v2=v3=-INFINITY; p0=p1=p2=p3=0;
                for (int t = 0; t < 32; t++) {
                    float nv = Sr[lane + 32 * t]; int np = lane + 32 * t;
                    if (nv > v3) {
                        if (nv > v1) {
                            if (nv > v0) { v3=v2;p3=p2; v2=v1;p2=p1; v1=v0;p1=p0; v0=nv;p0=np; }
                            else         { v3=v2;p3=p2; v2=v1;p2=p1; v1=nv;p1=np; }
                        } else {
                            if (nv > v2) { v3=v2;p3=p2; v2=nv;p2=np; }
                            else         { v3=nv;p3=np; }
                        }
                    }
                }
                cnt = 4;
            }
        }

        for (int it = 1; it < TOPK; it++) {
            kb = fmono(v0);
            mk = __reduce_max_sync(0xffffffffu, kb);
            cp = (kb == mk) ? (unsigned)p0 : 0xffffffffu;
            bp = __reduce_min_sync(0xffffffffu, cp);
            if (lane == 0) {
                tpi[w * TOPK + it] = (int)bp;
                tpp[w * TOPK + it] = __expf(fdemono(mk) - m) * inv;
            }
            if ((bp & 31) == lane) {
                Sr[bp] = -INFINITY;
                v0=v1;p0=p1; v1=v2;p1=p2; v2=v3;p2=p3; v3=-INFINITY;
                if (--cnt == 0) {
                    v0=v1=v2=v3=-INFINITY; p0=p1=p2=p3=0;
                    for (int t = 0; t < 32; t++) {
                        float nv = Sr[lane + 32 * t]; int np = lane + 32 * t;
                        if (nv > v3) {
                            if (nv > v1) {
                                if (nv > v0) { v3=v2;p3=p2; v2=v1;p2=p1; v1=v0;p1=p0; v0=nv;p0=np; }
                                else         { v3=v2;p3=p2; v2=v1;p2=p1; v1=nv;p1=np; }
                            } else {
                                if (nv > v2) { v3=v2;p3=p2; v2=nv;p2=np; }
                                else         { v3=nv;p3=np; }
                            }
                        }
                    }
                    cnt = 4;
                }
            }
        }
    }
    __syncthreads();

    // ---- sparse ctx: 16-key gather per query row ----
    const int cr = w;
    const int d0 = lane * 2;
    float c0 = 0.f, c1 = 0.f;
#pragma unroll
    for (int i = 0; i < TOPK; i++) {
        const int   idx = tpi[cr * TOPK + i];
        const float p   = tpp[cr * TOPK + i];
        float2 a = *(const float2*)(vg + (long)idx * BE + base + d0);
        c0 = fmaf(p, a.x, c0); c1 = fmaf(p, a.y, c1);
    }
    *(float2*)(ctxg + (long)(qt * QT + cr) * BE + base + d0) = make_float2(c0, c1);
}

// =====================================================================
// launch
// =====================================================================
static const size_t ATTN_SMEM =
    (size_t)(QT * SP + KT * 64 + QT * KSP + QT * TOPK + QT * TOPK) * 4;

extern "C" void kernel_launch(void* const* d_in, const int* in_sizes, int n_in,
                              void* d_out, int out_size)
{
    const float* query  = (const float*)d_in[0];
    const float* key_in = (const float*)d_in[1];
    const float* value  = (const float*)d_in[2];
    const float* Wq = (const float*)d_in[3];
    const float* bq = (const float*)d_in[4];
    const float* Wk = (const float*)d_in[5];
    const float* bk = (const float*)d_in[6];
    const float* Wv = (const float*)d_in[7];
    const float* bv = (const float*)d_in[8];
    const float* Wo = (const float*)d_in[9];
    const float* bo = (const float*)d_in[10];
    float* out = (float*)d_out;

    float *pq, *pk, *pv, *pctx;
    cudaGetSymbolAddress((void**)&pq,   g_q);
    cudaGetSymbolAddress((void**)&pk,   g_k);
    cudaGetSymbolAddress((void**)&pv,   g_v);
    cudaGetSymbolAddress((void**)&pctx, g_ctx);

    cudaFuncSetAttribute(attn_kernel,
                         cudaFuncAttributeMaxDynamicSharedMemorySize,
                         (int)ATTN_SMEM);

    dim3 gg(ROWS / 128, DIN / 128, NB);
    group_gemm<<<gg, 256>>>(query,  Wq, bq, pq, SCALING);
    group_gemm<<<gg, 256>>>(key_in, Wk, bk, pk, 1.0f);
    group_gemm<<<gg, 256>>>(value,  Wv, bv, pv, 1.0f);

    dim3 ag(T_ / QT, B_ * H_);
    attn_kernel<<<ag, NTH, ATTN_SMEM>>>(pq, pk, pv, pctx);

    group_gemm<<<gg, 256>>>(pctx, Wo, bo, out, 1.0f);
}

// round 7
// speedup vs baseline: 1.1793x; 1.0931x over previous
#include <cuda_runtime.h>
#include <math.h>

#define T_   1024
#define B_   8
#define E_   1024
#define H_   16
#define HD   64
#define NB   4
#define DIN  256
#define TOPK 16
#define ROWS (T_*B_)          // 8192
#define BE   (B_*E_)          // 8192
#define SCALING 0.125f        // 64^-0.5

// ---------- scratch (device globals; no runtime allocation) ----------
__device__ float g_q[ROWS * E_];
__device__ float g_k[ROWS * E_];
__device__ float g_v[ROWS * E_];
__device__ float g_ctx[ROWS * E_];

// ---------- packed f32x2 helpers (exact lane-wise IEEE rn) ----------
__device__ __forceinline__ void dup2(unsigned long long& d, float f) {
    asm("mov.b64 %0, {%1, %1};" : "=l"(d) : "r"(__float_as_uint(f)));
}
__device__ __forceinline__ void fma2(unsigned long long& d,
                                     unsigned long long a,
                                     unsigned long long b,
                                     unsigned long long c) {
    asm("fma.rn.f32x2 %0, %1, %2, %3;" : "=l"(d) : "l"(a), "l"(b), "l"(c));
}
__device__ __forceinline__ void unpack2(float& lo, float& hi, unsigned long long p) {
    unsigned l, h;
    asm("mov.b64 {%0, %1}, %2;" : "=r"(l), "=r"(h) : "l"(p));
    lo = __uint_as_float(l); hi = __uint_as_float(h);
}

// =====================================================================
// Double-buffered block-diagonal GEMM core (BK=16, FFMA2; accumulation
// order identical to previous rounds -> bitwise-identical outputs)
// =====================================================================
__device__ __forceinline__ void gemm_core(
    const float* __restrict__ X, const float* __restrict__ W,
    const float* __restrict__ bias, float* __restrict__ Y,
    float scale, int nb)
{
    const int m0 = blockIdx.x * 128;
    const int n0 = blockIdx.y * 128;
    const float* Wn = W + nb * DIN * DIN;

    __shared__ __align__(16) float As[2][16][128];
    __shared__ __align__(16) float Bs[2][16][128];

    const int tid = threadIdx.x;
    const int ty = tid >> 4;
    const int tx = tid & 15;
    const int arow = tid >> 1;
    const int akc  = (tid & 1) * 8;
    const int bkr  = tid >> 4;
    const int bcol = (tid & 15) * 8;

    const float* Xb = X + (long)m0 * E_ + nb * DIN;
    const float* Ap = Xb + (long)arow * E_;

    // prologue: stage 0
    {
        float4 a0 = *(const float4*)(Ap + akc);
        float4 a1 = *(const float4*)(Ap + akc + 4);
        float4 b0 = *(const float4*)(Wn + bkr * DIN + n0 + bcol);
        float4 b1 = *(const float4*)(Wn + bkr * DIN + n0 + bcol + 4);
        As[0][akc+0][arow] = a0.x; As[0][akc+1][arow] = a0.y;
        As[0][akc+2][arow] = a0.z; As[0][akc+3][arow] = a0.w;
        As[0][akc+4][arow] = a1.x; As[0][akc+5][arow] = a1.y;
        As[0][akc+6][arow] = a1.z; As[0][akc+7][arow] = a1.w;
        *(float4*)&Bs[0][bkr][bcol]     = b0;
        *(float4*)&Bs[0][bkr][bcol + 4] = b1;
    }
    __syncthreads();

    unsigned long long accp[8][4];
#pragma unroll
    for (int i = 0; i < 8; i++)
#pragma unroll
        for (int j = 0; j < 4; j++) accp[i][j] = 0ull;

    for (int k0 = 0; k0 < 16; k0++) {
        const int cur = k0 & 1;
        float4 a0, a1, b0, b1;
        if (k0 < 15) {
            const int kn = (k0 + 1) * 16;
            a0 = *(const float4*)(Ap + kn + akc);
            a1 = *(const float4*)(Ap + kn + akc + 4);
            b0 = *(const float4*)(Wn + (kn + bkr) * DIN + n0 + bcol);
            b1 = *(const float4*)(Wn + (kn + bkr) * DIN + n0 + bcol + 4);
        }
#pragma unroll
        for (int kk = 0; kk < 16; kk++) {
            float af[8];
            *(float4*)(af)     = *(const float4*)&As[cur][kk][ty * 8];
            *(float4*)(af + 4) = *(const float4*)&As[cur][kk][ty * 8 + 4];
            ulonglong2 bp0 = *(const ulonglong2*)&Bs[cur][kk][tx * 8];
            ulonglong2 bp1 = *(const ulonglong2*)&Bs[cur][kk][tx * 8 + 4];
#pragma unroll
            for (int i = 0; i < 8; i++) {
                unsigned long long aa;
                dup2(aa, af[i]);
                fma2(accp[i][0], aa, bp0.x, accp[i][0]);
                fma2(accp[i][1], aa, bp0.y, accp[i][1]);
                fma2(accp[i][2], aa, bp1.x, accp[i][2]);
                fma2(accp[i][3], aa, bp1.y, accp[i][3]);
            }
        }
        if (k0 < 15) {
            const int nxt = cur ^ 1;
            As[nxt][akc+0][arow] = a0.x; As[nxt][akc+1][arow] = a0.y;
            As[nxt][akc+2][arow] = a0.z; As[nxt][akc+3][arow] = a0.w;
            As[nxt][akc+4][arow] = a1.x; As[nxt][akc+5][arow] = a1.y;
            As[nxt][akc+6][arow] = a1.z; As[nxt][akc+7][arow] = a1.w;
            *(float4*)&Bs[nxt][bkr][bcol]     = b0;
            *(float4*)&Bs[nxt][bkr][bcol + 4] = b1;
        }
        __syncthreads();
    }

    float bj[8];
#pragma unroll
    for (int j = 0; j < 8; j++) bj[j] = bias[nb * DIN + n0 + tx * 8 + j];

#pragma unroll
    for (int i = 0; i < 8; i++) {
        float acc[8];
#pragma unroll
        for (int j = 0; j < 4; j++) unpack2(acc[2*j], acc[2*j+1], accp[i][j]);
        const long row = m0 + ty * 8 + i;
        float* yp = Y + row * E_ + nb * DIN + n0 + tx * 8;
        float4 o0, o1;
        o0.x = (acc[0] + bj[0]) * scale;
        o0.y = (acc[1] + bj[1]) * scale;
        o0.z = (acc[2] + bj[2]) * scale;
        o0.w = (acc[3] + bj[3]) * scale;
        o1.x = (acc[4] + bj[4]) * scale;
        o1.y = (acc[5] + bj[5]) * scale;
        o1.z = (acc[6] + bj[6]) * scale;
        o1.w = (acc[7] + bj[7]) * scale;
        *(float4*)yp       = o0;
        *(float4*)(yp + 4) = o1;
    }
}

// fused QKV: grid.z = 12 (op = z>>2, nb = z&3) -> 5.2 waves, less tail
__global__ void __launch_bounds__(256) qkv_gemm(
    const float* __restrict__ Q, const float* __restrict__ Kin,
    const float* __restrict__ V,
    const float* __restrict__ Wq, const float* __restrict__ bq,
    const float* __restrict__ Wk, const float* __restrict__ bk,
    const float* __restrict__ Wv, const float* __restrict__ bv,
    float* __restrict__ Yq, float* __restrict__ Yk, float* __restrict__ Yv)
{
    const int op = blockIdx.z >> 2;
    const int nb = blockIdx.z & 3;
    if (op == 0)      gemm_core(Q,   Wq, bq, Yq, SCALING, nb);
    else if (op == 1) gemm_core(Kin, Wk, bk, Yk, 1.0f,    nb);
    else              gemm_core(V,   Wv, bv, Yv, 1.0f,    nb);
}

__global__ void __launch_bounds__(256) o_gemm(
    const float* __restrict__ X, const float* __restrict__ W,
    const float* __restrict__ bias, float* __restrict__ Y)
{
    gemm_core(X, W, bias, Y, 1.0f, blockIdx.z);
}

// =====================================================================
// Fused attention. QT=16 queries/block, 512 threads, 2 blocks/SM.
// Scores: 4 warps, q-pair FFMA2 (each f32x2 lane = independent exact
// d-ascending fmaf chain -> bitwise-identical scores). K tile in R6
// swizzled key-major layout. Top-k/softmax/ctx unchanged mechanisms.
// =====================================================================
#define QT  16
#define KT  128
#define SP  1032
#define NTH 512

__device__ __forceinline__ unsigned fmono(float f) {
    unsigned b = __float_as_uint(f);
    return (b & 0x80000000u) ? ~b : (b | 0x80000000u);
}
__device__ __forceinline__ float fdemono(unsigned m) {
    unsigned b = (m & 0x80000000u) ? (m & 0x7fffffffu) : ~m;
    return __uint_as_float(b);
}

__global__ void __launch_bounds__(NTH, 2) attn_kernel(
    const float* __restrict__ qg, const float* __restrict__ kg,
    const float* __restrict__ vg, float* __restrict__ ctxg)
{
    extern __shared__ float sm[];
    float* S    = sm;                      // QT*SP           (66048 B)
    float* ks   = S + QT * SP;             // KT*64 swizzled  (32768 B)
    float* qp   = ks + KT * 64;            // 64 d x 8 pairs x float2 (4096 B)
    float* tpp  = qp + 64 * 8 * 2;         // QT*16
    int*   tpi  = (int*)(tpp + QT * TOPK); // QT*16

    const int tid = threadIdx.x;
    const int qt  = blockIdx.x;            // 0..63
    const int bh  = blockIdx.y;            // 0..127
    const int bb  = bh >> 4;
    const int hh  = bh & 15;
    const long base = (long)bb * E_ + hh * HD;

    const int lane = tid & 31;
    const int w    = tid >> 5;             // warp 0..15

    // ---- build q pairs: qp[d*8+p] = {q[2p][d], q[2p+1][d]} ----
    {
        const int p = tid >> 6;            // 0..7
        const int d = tid & 63;
        const float* q0 = qg + (long)(qt * QT + 2 * p) * BE + base + d;
        *(float2*)&qp[(d * 8 + p) * 2] = make_float2(q0[0], q0[BE]);
    }

    // score warp roles (w<4): g = q-pair group, s = key half
    const int g = (w >> 1) & 1;
    const int s = w & 1;
    const int lane7 = lane & 7;
    const float* ka_ptr = ks + (s * 64 + lane) * 64;
    const float* kb_ptr = ka_ptr + 32 * 64;

    for (int kt = 0; kt < T_ / KT; kt++) {
        __syncthreads();
        for (int f = tid; f < KT * 16; f += NTH) {
            int key = f >> 4, d4x = f & 15;
            float4 v4 = *(const float4*)(kg + (long)(kt * KT + key) * BE + base + d4x * 4);
            *(float4*)&ks[key * 64 + ((d4x ^ (key & 7)) << 2)] = v4;
        }
        __syncthreads();

        if (w < 4) {
            unsigned long long acc[4][2];
#pragma unroll
            for (int p = 0; p < 4; p++) { acc[p][0] = 0ull; acc[p][1] = 0ull; }

#pragma unroll 4
            for (int d4 = 0; d4 < 16; d4++) {
                const int c = (d4 ^ lane7) << 2;
                float4 Ka = *(const float4*)(ka_ptr + c);
                float4 Kb = *(const float4*)(kb_ptr + c);
#pragma unroll
                for (int dd = 0; dd < 4; dd++) {
                    unsigned long long kda, kdb;
                    dup2(kda, (&Ka.x)[dd]);
                    dup2(kdb, (&Kb.x)[dd]);
                    const float* qpd = qp + (((d4 * 4 + dd) * 8) + g * 4) * 2;
#pragma unroll
                    for (int p = 0; p < 4; p++) {
                        unsigned long long qv =
                            *(const unsigned long long*)(qpd + p * 2);
                        fma2(acc[p][0], qv, kda, acc[p][0]);
                        fma2(acc[p][1], qv, kdb, acc[p][1]);
                    }
                }
            }

            const int col = kt * KT + s * 64 + lane;
#pragma unroll
            for (int p = 0; p < 4; p++) {
                float lo, hi;
                unpack2(lo, hi, acc[p][0]);
                S[(g * 8 + 2 * p    ) * SP + col] = lo;
                S[(g * 8 + 2 * p + 1) * SP + col] = hi;
                unpack2(lo, hi, acc[p][1]);
                S[(g * 8 + 2 * p    ) * SP + col + 32] = lo;
                S[(g * 8 + 2 * p + 1) * SP + col + 32] = hi;
            }
        }
    }
    __syncthreads();

    // ---- per-row top-16 + softmax: warp w owns row w ----
    {
        float* Sr = S + w * SP;

        float v0 = -INFINITY, v1 = -INFINITY, v2 = -INFINITY, v3 = -INFINITY;
        int   p0 = 0, p1 = 0, p2 = 0, p3 = 0;
#pragma unroll 8
        for (int t = 0; t < 32; t++) {
            float nv = Sr[lane + 32 * t]; int np = lane + 32 * t;
            if (nv > v3) {
                if (nv > v1) {
                    if (nv > v0) { v3=v2;p3=p2; v2=v1;p2=p1; v1=v0;p1=p0; v0=nv;p0=np; }
                    else         { v3=v2;p3=p2; v2=v1;p2=p1; v1=nv;p1=np; }
                } else {
                    if (nv > v2) { v3=v2;p3=p2; v2=nv;p2=np; }
                    else         { v3=nv;p3=np; }
                }
            }
        }
        int cnt = 4;

        unsigned kb = fmono(v0);
        unsigned mk = __reduce_max_sync(0xffffffffu, kb);
        unsigned cp = (kb == mk) ? (unsigned)p0 : 0xffffffffu;
        unsigned bp = __reduce_min_sync(0xffffffffu, cp);
        const float m = fdemono(mk);

        float s0 = 0.f, s1 = 0.f, s2 = 0.f, s3 = 0.f;
#pragma unroll
        for (int t = 0; t < 32; t += 4) {
            s0 += __expf(Sr[lane + 32 * (t + 0)] - m);
            s1 += __expf(Sr[lane + 32 * (t + 1)] - m);
            s2 += __expf(Sr[lane + 32 * (t + 2)] - m);
            s3 += __expf(Sr[lane + 32 * (t + 3)] - m);
        }
        float sum = (s0 + s1) + (s2 + s3);
#pragma unroll
        for (int o = 16; o; o >>= 1) sum += __shfl_xor_sync(~0u, sum, o);
        const float inv = 1.0f / sum;

        if (lane == 0) { tpi[w * TOPK] = (int)bp; tpp[w * TOPK] = inv; }
        if ((bp & 31) == lane) {
            Sr[bp] = -INFINITY;
            v0=v1;p0=p1; v1=v2;p1=p2; v2=v3;p2=p3; v3=-INFINITY;
            if (--cnt == 0) {
                v0=v1=v2=v3=-INFINITY; p0=p1=p2=p3=0;
                for (int t = 0; t < 32; t++) {
                    float nv = Sr[lane + 32 * t]; int np = lane + 32 * t;
                    if (nv > v3) {
                        if (nv > v1) {
                            if (nv > v0) { v3=v2;p3=p2; v2=v1;p2=p1; v1=v0;p1=p0; v0=nv;p0=np; }
                            else         { v3=v2;p3=p2; v2=v1;p2=p1; v1=nv;p1=np; }
                        } else {
                            if (nv > v2) { v3=v2;p3=p2; v2=nv;p2=np; }
                            else         { v3=nv;p3=np; }
                        }
                    }
                }
                cnt = 4;
            }
        }

        for (int it = 1; it < TOPK; it++) {
            kb = fmono(v0);
            mk = __reduce_max_sync(0xffffffffu, kb);
            cp = (kb == mk) ? (unsigned)p0 : 0xffffffffu;
            bp = __reduce_min_sync(0xffffffffu, cp);
            if (lane == 0) {
                tpi[w * TOPK + it] = (int)bp;
                tpp[w * TOPK + it] = __expf(fdemono(mk) - m) * inv;
            }
            if ((bp & 31) == lane) {
                Sr[bp] = -INFINITY;
                v0=v1;p0=p1; v1=v2;p1=p2; v2=v3;p2=p3; v3=-INFINITY;
                if (--cnt == 0) {
                    v0=v1=v2=v3=-INFINITY; p0=p1=p2=p3=0;
                    for (int t = 0; t < 32; t++) {
                        float nv = Sr[lane + 32 * t]; int np = lane + 32 * t;
                        if (nv > v3) {
                            if (nv > v1) {
                                if (nv > v0) { v3=v2;p3=p2; v2=v1;p2=p1; v1=v0;p1=p0; v0=nv;p0=np; }
                                else         { v3=v2;p3=p2; v2=v1;p2=p1; v1=nv;p1=np; }
                            } else {
                                if (nv > v2) { v3=v2;p3=p2; v2=nv;p2=np; }
                                else         { v3=nv;p3=np; }
                            }
                        }
                    }
                    cnt = 4;
                }
            }
        }
    }
    __syncthreads();

    // ---- sparse ctx: 16-key gather; 32 threads x float2 per row ----
    const int cr = tid >> 5;               // 0..15 query row (== w)
    const int d0 = (tid & 31) * 2;
    float c0 = 0.f, c1 = 0.f;
#pragma unroll
    for (int i = 0; i < TOPK; i++) {
        const int   idx = tpi[cr * TOPK + i];
        const float p   = tpp[cr * TOPK + i];
        float2 a = *(const float2*)(vg + (long)idx * BE + base + d0);
        c0 = fmaf(p, a.x, c0); c1 = fmaf(p, a.y, c1);
    }
    *(float2*)(ctxg + (long)(qt * QT + cr) * BE + base + d0) = make_float2(c0, c1);
}

// =====================================================================
// launch
// =====================================================================
static const size_t ATTN_SMEM =
    (size_t)(QT * SP + KT * 64 + 64 * 8 * 2 + QT * TOPK + QT * TOPK) * 4;

extern "C" void kernel_launch(void* const* d_in, const int* in_sizes, int n_in,
                              void* d_out, int out_size)
{
    const float* query  = (const float*)d_in[0];
    const float* key_in = (const float*)d_in[1];
    const float* value  = (const float*)d_in[2];
    const float* Wq = (const float*)d_in[3];
    const float* bq = (const float*)d_in[4];
    const float* Wk = (const float*)d_in[5];
    const float* bk = (const float*)d_in[6];
    const float* Wv = (const float*)d_in[7];
    const float* bv = (const float*)d_in[8];
    const float* Wo = (const float*)d_in[9];
    const float* bo = (const float*)d_in[10];
    float* out = (float*)d_out;

    float *pq, *pk, *pv, *pctx;
    cudaGetSymbolAddress((void**)&pq,   g_q);
    cudaGetSymbolAddress((void**)&pk,   g_k);
    cudaGetSymbolAddress((void**)&pv,   g_v);
    cudaGetSymbolAddress((void**)&pctx, g_ctx);

    cudaFuncSetAttribute(attn_kernel,
                         cudaFuncAttributeMaxDynamicSharedMemorySize,
                         (int)ATTN_SMEM);

    dim3 gq(ROWS / 128, DIN / 128, 12);
    qkv_gemm<<<gq, 256>>>(query, key_in, value,
                          Wq, bq, Wk, bk, Wv, bv, pq, pk, pv);

    dim3 ag(T_ / QT, B_ * H_);
    attn_kernel<<<ag, NTH, ATTN_SMEM>>>(pq, pk, pv, pctx);

    dim3 go(ROWS / 128, DIN / 128, NB);
    o_gemm<<<go, 256>>>(pctx, Wo, bo, out);
}